// round 12
// baseline (speedup 1.0000x reference)
#include <cuda_runtime.h>
#include <cuda_bf16.h>
#include <math.h>
#include <stdint.h>

#define TT 65536
#define DD 256
#define RR 32
#define MM 52
#define CC 64
#define NCK 1024
#define SEG 16
#define NSEG (NCK/SEG)   // 64

// Scratch (device globals; no allocation allowed)
__device__ __align__(16) __nv_bfloat16 g_Qb [TT*RR];   // Lambda_u * q_u   [t][r]
__device__ __align__(16) __nv_bfloat16 g_Kb [TT*RR];   // (l/Lambda)*k     [t][r]
__device__ __align__(16) __nv_bfloat16 g_VTb[TT*RR];   // per-chunk V^T    [chunk][j=32][u=64]
__device__ __align__(16) float g_BT [NCK*RR*RR];       // per-chunk (K~^T V)^T  [chunk][j][i]
__device__ float g_gm[NCK];                            // per-chunk Lambda_C
__device__ __align__(16) float g_carry[NSEG*1024];     // segment-local carries

__device__ __forceinline__ uint32_t packbf(float a, float b) {
    __nv_bfloat162 h = __floats2bfloat162_rn(a, b);
    return *reinterpret_cast<uint32_t*>(&h);
}
__device__ __forceinline__ float tanh_fast(float x) {
    float y; asm("tanh.approx.f32 %0, %1;" : "=f"(y) : "f"(x)); return y;
}
__device__ __forceinline__ void mma16816(float* c, const uint32_t* a, const uint32_t* b) {
    asm volatile("mma.sync.aligned.m16n8k16.row.col.f32.bf16.bf16.f32 "
        "{%0,%1,%2,%3}, {%4,%5,%6,%7}, {%8,%9}, {%0,%1,%2,%3};"
        : "+f"(c[0]), "+f"(c[1]), "+f"(c[2]), "+f"(c[3])
        : "r"(a[0]), "r"(a[1]), "r"(a[2]), "r"(a[3]), "r"(b[0]), "r"(b[1]));
}

#define FB_STRIDE 20            // floats per row (80B, 16B-multiple)
#define FB_ELEMS  (128*FB_STRIDE)  // 2560 floats per buffer
#define NBUF 5

// Issue one k16 step (16 cols of X, 128 rows) as 2 cp.async.16B per thread.
__device__ __forceinline__ void cp_step(const float* __restrict__ X, int t0,
                                        uint32_t fb32, int tid, int s) {
    const float* gbase = X + (size_t)t0*DD + 16*s;
    uint32_t sbase = fb32 + (uint32_t)(s % NBUF) * (FB_ELEMS*4u);
    #pragma unroll
    for (int r = 0; r < 2; r++) {
        int c = tid + 256*r;                 // 512 chunks of 16B
        int row = c >> 2, col4 = (c & 3) << 2;
        uint32_t sa = sbase + (uint32_t)(row*FB_STRIDE + col4)*4u;
        asm volatile("cp.async.cg.shared.global [%0], [%1], 16;\n"
            :: "r"(sa), "l"(gbase + (size_t)row*DD + col4));
    }
}
#define CP_COMMIT() asm volatile("cp.async.commit_group;\n" ::: "memory")
#define CP_WAIT(n)  asm volatile("cp.async.wait_group %0;\n" :: "n"(n) : "memory")

// ---------------------------------------------------------------------------
// Kernel 1: 2 chunks (128 rows) per block. bf16 MMA projections + B + gamma.
// X streamed via cp.async (fp32 smem ring, depth 3); bf16 cvt at frag load.
// W preloaded once (96x264 bf16). All global stores smem-staged + coalesced.
// ---------------------------------------------------------------------------
__global__ __launch_bounds__(256, 2) void k_proj(
    const float* __restrict__ X,  const float* __restrict__ lr,
    const float* __restrict__ dec,
    const float* __restrict__ Wk, const float* __restrict__ bk,
    const float* __restrict__ Wv, const float* __restrict__ bv,
    const float* __restrict__ Wq, const float* __restrict__ bq)
{
    extern __shared__ __align__(16) __nv_bfloat16 dsm[];
    __nv_bfloat16* sW  = dsm;                      // 96 x 264 bf16 = 50688 B
    float*        fbuf = (float*)(dsm + 96*264);   // 5 x 128x20 fp32 = 51200 B
    __shared__ float Lam[128], Lrs[128], Dcs[128], bcat[96];

    const int tid  = threadIdx.x;
    const int lane = tid & 31, w = tid >> 5;
    const int g = lane >> 2, tig = lane & 3;
    const int t0 = blockIdx.x * 128;
    const uint32_t fb32 = (uint32_t)__cvta_generic_to_shared(fbuf);

    if (tid < 96)
        bcat[tid] = (tid < 32) ? bk[tid] : (tid < 64 ? bv[tid-32] : bq[tid-64]);
    if (tid < 128) Lrs[tid] = lr[t0 + tid];
    else           Dcs[tid-128] = dec[t0 + tid - 128];

    // Get the X stream going immediately (depth 3)
    cp_step(X, t0, fb32, tid, 0); CP_COMMIT();
    cp_step(X, t0, fb32, tid, 1); CP_COMMIT();
    cp_step(X, t0, fb32, tid, 2); CP_COMMIT();

    // Preload full W (96x256 f32 -> bf16), 24 float4 per thread (overlaps stream)
    #pragma unroll
    for (int r = 0; r < 24; r++) {
        int slot = tid + 256*r;                  // 6144 slots
        int row = slot >> 6, k4 = (slot & 63) << 2;
        const float* Wsrc = (row < 32) ? Wk : (row < 64 ? Wv : Wq);
        float4 w4 = *(const float4*)&Wsrc[(row & 31)*DD + k4];
        uint2 p; p.x = packbf(w4.x, w4.y); p.y = packbf(w4.z, w4.w);
        *(uint2*)&sW[row*264 + k4] = p;
    }

    __syncthreads();           // Dcs visible
    if (tid < 2) {
        float p = 1.f;
        #pragma unroll
        for (int u = 0; u < 64; u++) { p *= (1.f - Dcs[64*tid + u]); Lam[64*tid + u] = p; }
    }

    const int wy = w >> 1, wx = w & 1;   // warp tile: 32 rows x 48 cols
    float acc[2][6][4];
    #pragma unroll
    for (int mi = 0; mi < 2; mi++)
        #pragma unroll
        for (int ni = 0; ni < 6; ni++)
            #pragma unroll
            for (int r = 0; r < 4; r++) acc[mi][ni][r] = 0.f;

    // ---- 16-step k16 pipeline ----
    #pragma unroll
    for (int s = 0; s < 16; s++) {
        if (s + 3 < 16) { cp_step(X, t0, fb32, tid, s + 3); CP_COMMIT(); }
        if      (s <= 12) CP_WAIT(3);
        else if (s == 13) CP_WAIT(2);
        else if (s == 14) CP_WAIT(1);
        else              CP_WAIT(0);
        __syncthreads();   // buffer s%NBUF full for all threads (also W/Lam on s=0)

        const float* bufp = fbuf + (s % NBUF) * FB_ELEMS;
        uint32_t a[2][4];
        #pragma unroll
        for (int mi = 0; mi < 2; mi++) {
            int rb = wy*32 + mi*16;
            float2 p0 = *(const float2*)&bufp[(rb+g  )*FB_STRIDE +     2*tig];
            float2 p1 = *(const float2*)&bufp[(rb+8+g)*FB_STRIDE +     2*tig];
            float2 p2 = *(const float2*)&bufp[(rb+g  )*FB_STRIDE + 8 + 2*tig];
            float2 p3 = *(const float2*)&bufp[(rb+8+g)*FB_STRIDE + 8 + 2*tig];
            a[mi][0] = packbf(p0.x, p0.y);
            a[mi][1] = packbf(p1.x, p1.y);
            a[mi][2] = packbf(p2.x, p2.y);
            a[mi][3] = packbf(p3.x, p3.y);
        }
        int kbW = s * 16;
        #pragma unroll
        for (int ni = 0; ni < 6; ni++) {
            int nb = wx*48 + ni*8;
            uint32_t b[2];
            b[0] = *(const uint32_t*)&sW[(nb+g)*264 + kbW +     2*tig];
            b[1] = *(const uint32_t*)&sW[(nb+g)*264 + kbW + 8 + 2*tig];
            mma16816(acc[0][ni], a[0], b);
            mma16816(acc[1][ni], a[1], b);
        }
    }
    __syncthreads();   // all MMA reads of sW/fbuf done before epilogue overwrites

    // Staging regions (all smem-only writes in the epilogue):
    __nv_bfloat16* KsT  = (__nv_bfloat16*)fbuf;       // [2][32][72] K~^T
    __nv_bfloat16* VsT  = KsT + 2*32*72;              // [2][32][72] V^T
    __nv_bfloat16* Qrow = sW;                         // [128][40]   Q~ row-major
    __nv_bfloat16* Krow = sW + 128*40;                // [128][40]   K~ row-major
    float*         Bst  = (float*)(sW + 2*128*40);    // [2][32][36] B^T fp32

    #pragma unroll
    for (int mi = 0; mi < 2; mi++) {
        int rlo = wy*32 + mi*16 + g, rhi = rlo + 8;
        float lamL = Lam[rlo], lamH = Lam[rhi];
        float ksL = Lrs[rlo]/lamL, ksH = Lrs[rhi]/lamH;
        int chL = rlo >> 6, ulL = rlo & 63;
        int chH = rhi >> 6, ulH = rhi & 63;
        #pragma unroll
        for (int ni = 0; ni < 6; ni++) {
            int c0 = wx*48 + ni*8 + 2*tig;
            float v0 = acc[mi][ni][0] + bcat[c0];
            float v1 = acc[mi][ni][1] + bcat[c0+1];
            float v2 = acc[mi][ni][2] + bcat[c0];
            float v3 = acc[mi][ni][3] + bcat[c0+1];
            if (c0 < 32) {
                v0 *= ksL; v1 *= ksL; v2 *= ksH; v3 *= ksH;
                *(uint32_t*)&Krow[rlo*40 + c0] = packbf(v0, v1);
                *(uint32_t*)&Krow[rhi*40 + c0] = packbf(v2, v3);
                KsT[(chL*32 + c0  )*72 + ulL] = __float2bfloat16(v0);
                KsT[(chL*32 + c0+1)*72 + ulL] = __float2bfloat16(v1);
                KsT[(chH*32 + c0  )*72 + ulH] = __float2bfloat16(v2);
                KsT[(chH*32 + c0+1)*72 + ulH] = __float2bfloat16(v3);
            } else if (c0 < 64) {
                int j0 = c0 - 32;
                VsT[(chL*32 + j0  )*72 + ulL] = __float2bfloat16(v0);
                VsT[(chL*32 + j0+1)*72 + ulL] = __float2bfloat16(v1);
                VsT[(chH*32 + j0  )*72 + ulH] = __float2bfloat16(v2);
                VsT[(chH*32 + j0+1)*72 + ulH] = __float2bfloat16(v3);
            } else {
                int r0 = c0 - 64;
                *(uint32_t*)&Qrow[rlo*40 + r0] = packbf(v0*lamL, v1*lamL);
                *(uint32_t*)&Qrow[rhi*40 + r0] = packbf(v2*lamH, v3*lamH);
            }
        }
    }
    __syncthreads();

    // B^T = (K~^T V)^T via MMA: per chunk 4 warps, warp tile m16 x n16, k=64
    {
        int ch = w >> 2, wl = w & 3;
        int wy2 = wl >> 1, wx2 = wl & 1;
        const __nv_bfloat16* Kt = KsT + ch*32*72;
        const __nv_bfloat16* Vt = VsT + ch*32*72;
        float accB[2][4];
        #pragma unroll
        for (int ni = 0; ni < 2; ni++)
            #pragma unroll
            for (int r = 0; r < 4; r++) accB[ni][r] = 0.f;
        #pragma unroll
        for (int ks = 0; ks < 4; ks++) {
            int kb = ks * 16;
            int rb2 = wy2 * 16;
            uint32_t a[4];
            a[0] = *(const uint32_t*)&Kt[(rb2+g  )*72 + kb +     2*tig];
            a[1] = *(const uint32_t*)&Kt[(rb2+8+g)*72 + kb +     2*tig];
            a[2] = *(const uint32_t*)&Kt[(rb2+g  )*72 + kb + 8 + 2*tig];
            a[3] = *(const uint32_t*)&Kt[(rb2+8+g)*72 + kb + 8 + 2*tig];
            #pragma unroll
            for (int ni = 0; ni < 2; ni++) {
                int nb = wx2*16 + ni*8;
                uint32_t b[2];
                b[0] = *(const uint32_t*)&Vt[(nb+g)*72 + kb +     2*tig];
                b[1] = *(const uint32_t*)&Vt[(nb+g)*72 + kb + 8 + 2*tig];
                mma16816(accB[ni], a, b);
            }
        }
        float* Bc = Bst + ch*32*36;
        #pragma unroll
        for (int ni = 0; ni < 2; ni++) {
            int i0 = wy2*16 + g, i1 = i0 + 8;
            int j0 = wx2*16 + ni*8 + 2*tig;
            Bc[(j0  )*36 + i0] = accB[ni][0];
            Bc[(j0+1)*36 + i0] = accB[ni][1];
            Bc[(j0  )*36 + i1] = accB[ni][2];
            Bc[(j0+1)*36 + i1] = accB[ni][3];
        }
        if (wl == 0 && lane == 0) g_gm[blockIdx.x*2 + ch] = Lam[ch*64 + 63];
    }
    __syncthreads();

    // ---- Coalesced flush: smem -> gmem, all uint4/float4 ----
    #pragma unroll
    for (int r = 0; r < 2; r++) {
        int slot = tid + 256*r;               // 512 slots
        {   // Q, K rows: 128 rows x 32 bf16 = 4 x 16B per row
            int row = slot >> 2, q8 = (slot & 3) << 3;
            size_t dst = (size_t)(t0 + row)*RR + q8;
            *(uint4*)&g_Qb[dst] = *(const uint4*)&Qrow[row*40 + q8];
            *(uint4*)&g_Kb[dst] = *(const uint4*)&Krow[row*40 + q8];
        }
        {   // V^T: 64 rows (2ch x 32) x 64 bf16 = 8 x 16B per row
            int rr = slot >> 3, i8 = (slot & 7) << 3;
            *(uint4*)&g_VTb[(size_t)blockIdx.x*4096 + rr*64 + i8] =
                *(const uint4*)&VsT[rr*72 + i8];
        }
        {   // B^T: 64 rows (2ch x 32) x 32 fp32 = 8 x 16B per row
            int rr = slot >> 3, ch = rr >> 5, j = rr & 31, i4 = (slot & 7) << 2;
            *(float4*)&g_BT[(size_t)(blockIdx.x*2 + ch)*1024 + j*32 + i4] =
                *(const float4*)&Bst[ch*1152 + j*36 + i4];
        }
    }
}

// ---------------------------------------------------------------------------
// Scan phase A: per-segment local carry (zero init), depth 16.
// ---------------------------------------------------------------------------
__global__ __launch_bounds__(1024, 1) void k_scan_a()
{
    __shared__ float gs[SEG];
    const int b = blockIdx.x, e = threadIdx.x;
    if (e < SEG) gs[e] = g_gm[b*SEG + e];
    __syncthreads();
    const float* Bp = g_BT + (size_t)b*SEG*1024 + e;
    float bvv[SEG];
    #pragma unroll
    for (int c = 0; c < SEG; c++) bvv[c] = Bp[(size_t)c*1024];
    float s = 0.f;
    #pragma unroll
    for (int c = 0; c < SEG; c++) s = gs[c] * (s + bvv[c]);
    g_carry[(size_t)b*1024 + e] = s;
}

// ---------------------------------------------------------------------------
// Kernel 3 (fused with scan phase B): 4 chunks/block, grid 256 = single wave.
// ---------------------------------------------------------------------------
__global__ __launch_bounds__(256, 3) void k_out(
    const float* __restrict__ Wo, const float* __restrict__ bo,
    float* __restrict__ out)
{
    extern __shared__ __align__(16) __nv_bfloat16 osm[];
    __nv_bfloat16* sQ  = osm;                 // 4*64*40 = 10240
    __nv_bfloat16* sK  = sQ  + 10240;         // 10240
    __nv_bfloat16* sVT = sK  + 10240;         // 4*32*72 = 9216
    __nv_bfloat16* sST = sVT + 9216;          // 4*32*40 = 5120
    __nv_bfloat16* sWo = sST + 5120;          // 56*40   = 2240
    __shared__ float sbo[56];
    __shared__ float sAs[NSEG];
    __shared__ float gsc[SEG];

    const int tid   = threadIdx.x;
    const int cg0   = blockIdx.x * 4;         // first chunk of this block
    const int b_seg = blockIdx.x >> 2;        // segment index
    const int p0    = (blockIdx.x & 3) * 4;   // seg-local offset of cg0

    if (tid < NSEG) {
        float pp = 1.f;
        #pragma unroll
        for (int c = 0; c < SEG; c++) pp *= g_gm[tid*SEG + c];
        sAs[tid] = pp;
    } else if (tid < NSEG + SEG) {
        gsc[tid - NSEG] = g_gm[b_seg*SEG + (tid - NSEG)];
    } else if (tid < NSEG + SEG + 56) {
        int m = tid - NSEG - SEG;
        sbo[m] = (m < MM) ? bo[m] : 0.f;
    }

    #pragma unroll
    for (int r = 0; r < 8; r++) {
        int slot = tid + 256*r;                 // 2048 slots
        int ch = slot >> 9, s = slot & 511;
        int row = s >> 3, c4 = (s & 7) << 2;
        size_t gi = ((size_t)(cg0+ch)*64 + row)*RR + c4;
        *(uint2*)&sQ[(ch*64+row)*40 + c4] = *(const uint2*)&g_Qb[gi];
        *(uint2*)&sK[(ch*64+row)*40 + c4] = *(const uint2*)&g_Kb[gi];
    }
    #pragma unroll
    for (int r = 0; r < 8; r++) {
        int slot = tid + 256*r;                 // 2048 slots
        int ch = slot >> 9, s = slot & 511;
        int row = s >> 4, c4 = (s & 15) << 2;
        *(uint2*)&sVT[(ch*32+row)*72 + c4] =
            *(const uint2*)&g_VTb[(size_t)(cg0+ch)*2048 + row*64 + c4];
    }
    #pragma unroll
    for (int r = 0; r < 7; r++) {
        int idx = tid + 256*r;                  // 1792 = 56*32
        int m = idx >> 5, jj = idx & 31;
        sWo[m*40 + jj] = __float2bfloat16(m < MM ? Wo[m*RR + jj] : 0.f);
    }
    __syncthreads();

    // ---- Fold carries of preceding segments
    float pf[4] = {0.f, 0.f, 0.f, 0.f};
    for (int bb = 0; bb < b_seg; bb += 8) {
        float4 cv[8]; float av[8];
        #pragma unroll
        for (int jq = 0; jq < 8; jq++) {
            bool ok = (bb + jq) < b_seg;
            cv[jq] = ok ? *(const float4*)&g_carry[(size_t)(bb+jq)*1024 + tid*4]
                        : make_float4(0.f, 0.f, 0.f, 0.f);
            av[jq] = ok ? sAs[bb+jq] : 1.f;
        }
        #pragma unroll
        for (int jq = 0; jq < 8; jq++) {
            pf[0] = fmaf(av[jq], pf[0], cv[jq].x);
            pf[1] = fmaf(av[jq], pf[1], cv[jq].y);
            pf[2] = fmaf(av[jq], pf[2], cv[jq].z);
            pf[3] = fmaf(av[jq], pf[3], cv[jq].w);
        }
    }
    // ---- Replay seg-local chunks 0..p0-1
    for (int cc = 0; cc < p0; cc += 4) {
        float4 bv[4];
        #pragma unroll
        for (int jq = 0; jq < 4; jq++)
            bv[jq] = *(const float4*)&g_BT[(size_t)(b_seg*SEG + cc + jq)*1024 + tid*4];
        #pragma unroll
        for (int jq = 0; jq < 4; jq++) {
            float gv = gsc[cc + jq];
            pf[0] = gv*(pf[0] + bv[jq].x);
            pf[1] = gv*(pf[1] + bv[jq].y);
            pf[2] = gv*(pf[2] + bv[jq].z);
            pf[3] = gv*(pf[3] + bv[jq].w);
        }
    }
    // ---- Emit 4 incoming states into sST (bf16)
    {
        const int jrow = tid >> 3, i0 = (tid & 7) << 2;
        float4 b3[3];
        #pragma unroll
        for (int q = 0; q < 3; q++)
            b3[q] = *(const float4*)&g_BT[(size_t)(cg0 + q)*1024 + tid*4];
        __nv_bfloat16* d0 = &sST[(0*32 + jrow)*40 + i0];
        *(uint32_t*)&d0[0] = packbf(pf[0], pf[1]);
        *(uint32_t*)&d0[2] = packbf(pf[2], pf[3]);
        #pragma unroll
        for (int q = 0; q < 3; q++) {
            float gv = gsc[p0 + q];
            pf[0] = gv*(pf[0] + b3[q].x);
            pf[1] = gv*(pf[1] + b3[q].y);
            pf[2] = gv*(pf[2] + b3[q].z);
            pf[3] = gv*(pf[3] + b3[q].w);
            __nv_bfloat16* d = &sST[((q+1)*32 + jrow)*40 + i0];
            *(uint32_t*)&d[0] = packbf(pf[0], pf[1]);
            *(uint32_t*)&d[2] = packbf(pf[2], pf[3]);
        }
    }
    __syncthreads();

    // ---- MMA phase: 8 warps, each does 2 chunks sequentially
    const int lane = tid & 31, w = tid >> 5;
    const int g = lane >> 2, tig = lane & 3;
    const int rb = (w & 3) * 16;

    for (int ch2 = 0; ch2 < 2; ch2++) {
        const int ci = (w >> 2)*2 + ch2;
        const __nv_bfloat16* Q  = sQ  + ci*2560;
        const __nv_bfloat16* K  = sK  + ci*2560;
        const __nv_bfloat16* VT = sVT + ci*2304;
        const __nv_bfloat16* ST = sST + ci*1280;

        uint32_t aq[2][4];
        float accA[8][4];
        #pragma unroll
        for (int ni = 0; ni < 8; ni++)
            #pragma unroll
            for (int r = 0; r < 4; r++) accA[ni][r] = 0.f;
        #pragma unroll
        for (int ks = 0; ks < 2; ks++) {
            int kb = ks * 16;
            aq[ks][0] = *(const uint32_t*)&Q[(rb+g  )*40 + kb +     2*tig];
            aq[ks][1] = *(const uint32_t*)&Q[(rb+8+g)*40 + kb +     2*tig];
            aq[ks][2] = *(const uint32_t*)&Q[(rb+g  )*40 + kb + 8 + 2*tig];
            aq[ks][3] = *(const uint32_t*)&Q[(rb+8+g)*40 + kb + 8 + 2*tig];
            #pragma unroll
            for (int ni = 0; ni < 8; ni++) {
                uint32_t b[2];
                b[0] = *(const uint32_t*)&K[(ni*8+g)*40 + kb +     2*tig];
                b[1] = *(const uint32_t*)&K[(ni*8+g)*40 + kb + 8 + 2*tig];
                mma16816(accA[ni], aq[ks], b);
            }
        }
        uint32_t aA[4][4];
        {
            int ulo = rb + g, uhi = rb + g + 8;
            #pragma unroll
            for (int ni = 0; ni < 8; ni++) {
                int s0 = ni*8 + 2*tig, s1 = s0 + 1;
                float m0 = (s0 <= ulo) ? accA[ni][0] : 0.f;
                float m1 = (s1 <= ulo) ? accA[ni][1] : 0.f;
                float m2 = (s0 <= uhi) ? accA[ni][2] : 0.f;
                float m3 = (s1 <= uhi) ? accA[ni][3] : 0.f;
                int ks2 = ni >> 1;
                if ((ni & 1) == 0) { aA[ks2][0] = packbf(m0, m1); aA[ks2][1] = packbf(m2, m3); }
                else               { aA[ks2][2] = packbf(m0, m1); aA[ks2][3] = packbf(m2, m3); }
            }
        }
        float accO[4][4];
        #pragma unroll
        for (int ni = 0; ni < 4; ni++)
            #pragma unroll
            for (int r = 0; r < 4; r++) accO[ni][r] = 0.f;
        #pragma unroll
        for (int ks = 0; ks < 2; ks++) {
            int kb = ks * 16;
            #pragma unroll
            for (int ni = 0; ni < 4; ni++) {
                uint32_t b[2];
                b[0] = *(const uint32_t*)&ST[(ni*8+g)*40 + kb +     2*tig];
                b[1] = *(const uint32_t*)&ST[(ni*8+g)*40 + kb + 8 + 2*tig];
                mma16816(accO[ni], aq[ks], b);
            }
        }
        #pragma unroll
        for (int ks = 0; ks < 4; ks++) {
            int kb = ks * 16;
            #pragma unroll
            for (int ni = 0; ni < 4; ni++) {
                uint32_t b[2];
                b[0] = *(const uint32_t*)&VT[(ni*8+g)*72 + kb +     2*tig];
                b[1] = *(const uint32_t*)&VT[(ni*8+g)*72 + kb + 8 + 2*tig];
                mma16816(accO[ni], aA[ks], b);
            }
        }
        uint32_t aO[2][4];
        #pragma unroll
        for (int ks2 = 0; ks2 < 2; ks2++) {
            aO[ks2][0] = packbf(accO[2*ks2  ][0], accO[2*ks2  ][1]);
            aO[ks2][1] = packbf(accO[2*ks2  ][2], accO[2*ks2  ][3]);
            aO[ks2][2] = packbf(accO[2*ks2+1][0], accO[2*ks2+1][1]);
            aO[ks2][3] = packbf(accO[2*ks2+1][2], accO[2*ks2+1][3]);
        }
        float accH[7][4];
        #pragma unroll
        for (int ni = 0; ni < 7; ni++)
            #pragma unroll
            for (int r = 0; r < 4; r++) accH[ni][r] = 0.f;
        #pragma unroll
        for (int ks = 0; ks < 2; ks++) {
            int kb = ks * 16;
            #pragma unroll
            for (int ni = 0; ni < 7; ni++) {
                uint32_t b[2];
                b[0] = *(const uint32_t*)&sWo[(ni*8+g)*40 + kb +     2*tig];
                b[1] = *(const uint32_t*)&sWo[(ni*8+g)*40 + kb + 8 + 2*tig];
                mma16816(accH[ni], aO[ks], b);
            }
        }
        {
            size_t t0c = (size_t)(cg0 + ci) * 64;
            size_t rl = (t0c + rb + g) * MM;
            size_t rh = (t0c + rb + g + 8) * MM;
            #pragma unroll
            for (int ni = 0; ni < 7; ni++) {
                int m0 = ni*8 + 2*tig, m1 = m0 + 1;
                if (m0 < MM) {
                    out[rl + m0] = 1.f + tanh_fast(accH[ni][0] + sbo[m0]);
                    out[rh + m0] = 1.f + tanh_fast(accH[ni][2] + sbo[m0]);
                }
                if (m1 < MM) {
                    out[rl + m1] = 1.f + tanh_fast(accH[ni][1] + sbo[m1]);
                    out[rh + m1] = 1.f + tanh_fast(accH[ni][3] + sbo[m1]);
                }
            }
        }
    }
}

// ---------------------------------------------------------------------------
extern "C" void kernel_launch(void* const* d_in, const int* in_sizes, int n_in,
                              void* d_out, int out_size)
{
    const float* X  = (const float*)d_in[0];
    const float* lr = (const float*)d_in[1];
    const float* dc = (const float*)d_in[2];
    const float* Wk = (const float*)d_in[3];
    const float* bk = (const float*)d_in[4];
    const float* Wv = (const float*)d_in[5];
    const float* bv = (const float*)d_in[6];
    const float* Wq = (const float*)d_in[7];
    const float* bq = (const float*)d_in[8];
    const float* Wo = (const float*)d_in[9];
    const float* bo = (const float*)d_in[10];
    float* out = (float*)d_out;

    const int smem1 = 96*264*2 + NBUF*FB_ELEMS*4;                 // 101888 B
    const int smem3 = (10240 + 10240 + 9216 + 5120 + 2240) * 2;   // 74112 B
    cudaFuncSetAttribute(k_proj, cudaFuncAttributeMaxDynamicSharedMemorySize, smem1);
    cudaFuncSetAttribute(k_out,  cudaFuncAttributeMaxDynamicSharedMemorySize, smem3);

    k_proj<<<NCK/2, 256, smem1>>>(X, lr, dc, Wk, bk, Wv, bv, Wq, bq);
    k_scan_a<<<NSEG, 1024>>>();
    k_out<<<NCK/4, 256, smem3>>>(Wo, bo, out);
    (void)in_sizes; (void)n_in; (void)out_size;
}

// round 13
// speedup vs baseline: 1.1491x; 1.1491x over previous
#include <cuda_runtime.h>
#include <cuda_bf16.h>
#include <math.h>
#include <stdint.h>

#define TT 65536
#define DD 256
#define RR 32
#define MM 52
#define CC 64
#define NCK 1024
#define SEG 16
#define NSEG (NCK/SEG)   // 64

// Scratch (device globals; no allocation allowed)
__device__ __align__(16) __nv_bfloat16 g_Qb [TT*RR];   // Lambda_u * q_u   [t][r]
__device__ __align__(16) __nv_bfloat16 g_Kb [TT*RR];   // (l/Lambda)*k     [t][r]
__device__ __align__(16) __nv_bfloat16 g_VTb[TT*RR];   // per-chunk V^T    [chunk][j=32][u=64]
__device__ __align__(16) float g_BT [NCK*RR*RR];       // per-chunk (K~^T V)^T  [chunk][j][i]
__device__ float g_gm[NCK];                            // per-chunk Lambda_C
__device__ __align__(16) float g_carry[NSEG*1024];     // segment-local carries

__device__ __forceinline__ uint32_t packbf(float a, float b) {
    __nv_bfloat162 h = __floats2bfloat162_rn(a, b);
    return *reinterpret_cast<uint32_t*>(&h);
}
__device__ __forceinline__ float tanh_fast(float x) {
    float y; asm("tanh.approx.f32 %0, %1;" : "=f"(y) : "f"(x)); return y;
}
__device__ __forceinline__ void mma16816(float* c, const uint32_t* a, const uint32_t* b) {
    asm volatile("mma.sync.aligned.m16n8k16.row.col.f32.bf16.bf16.f32 "
        "{%0,%1,%2,%3}, {%4,%5,%6,%7}, {%8,%9}, {%0,%1,%2,%3};"
        : "+f"(c[0]), "+f"(c[1]), "+f"(c[2]), "+f"(c[3])
        : "r"(a[0]), "r"(a[1]), "r"(a[2]), "r"(a[3]), "r"(b[0]), "r"(b[1]));
}
__device__ __forceinline__ void ldsm_x4(uint32_t* d, uint32_t saddr) {
    asm volatile("ldmatrix.sync.aligned.m8n8.x4.shared.b16 {%0,%1,%2,%3}, [%4];"
        : "=r"(d[0]), "=r"(d[1]), "=r"(d[2]), "=r"(d[3]) : "r"(saddr));
}
__device__ __forceinline__ void ldsm_x2(uint32_t* d, uint32_t saddr) {
    asm volatile("ldmatrix.sync.aligned.m8n8.x2.shared.b16 {%0,%1}, [%2];"
        : "=r"(d[0]), "=r"(d[1]) : "r"(saddr));
}
__device__ __forceinline__ uint32_t sptr(const void* p) {
    return (uint32_t)__cvta_generic_to_shared(p);
}

// ---------------------------------------------------------------------------
// Kernel 1: 2 chunks (128 rows) per block. bf16 MMA projections + B + gamma.
// W preloaded once; X software-pipelined via register prefetch; LDSM frags.
// ---------------------------------------------------------------------------
__global__ __launch_bounds__(256, 2) void k_proj(
    const float* __restrict__ X,  const float* __restrict__ lr,
    const float* __restrict__ dec,
    const float* __restrict__ Wk, const float* __restrict__ bk,
    const float* __restrict__ Wv, const float* __restrict__ bv,
    const float* __restrict__ Wq, const float* __restrict__ bq)
{
    extern __shared__ __align__(16) __nv_bfloat16 dsm[];
    __nv_bfloat16* sW = dsm;                 // 96 x 264  (full K=256 + pad 8)
    __nv_bfloat16* sX = dsm + 96*264;        // 128 x 72  (one 64-col k-slab)
    __shared__ float Lam[128], Lrs[128], Dcs[128], bcat[96];

    const int tid  = threadIdx.x;
    const int lane = tid & 31, w = tid >> 5;
    const int g = lane >> 2, tig = lane & 3;
    const int al = lane & 15, ah = 8*(lane >> 4);        // ldmatrix A lane addr
    const int bl = lane & 7,  bh = 8*((lane >> 3) & 1);  // ldmatrix B lane addr
    const int t0 = blockIdx.x * 128;
    const uint32_t sX32 = sptr(sX), sW32 = sptr(sW);

    if (tid < 96)
        bcat[tid] = (tid < 32) ? bk[tid] : (tid < 64 ? bv[tid-32] : bq[tid-64]);
    if (tid < 128) Lrs[tid] = lr[t0 + tid];
    else           Dcs[tid-128] = dec[t0 + tid - 128];

    // Prefetch X slab 0 into registers (8 float4 per thread)
    float4 R[8];
    #pragma unroll
    for (int r = 0; r < 8; r++) {
        int slot = tid + 256*r;
        int row = slot >> 4, k4 = (slot & 15) << 2;
        R[r] = *(const float4*)&X[(size_t)(t0+row)*DD + k4];
    }

    // Preload full W (96x256 f32 -> bf16), 24 float4 per thread
    #pragma unroll
    for (int r = 0; r < 24; r++) {
        int slot = tid + 256*r;                  // 6144 slots
        int row = slot >> 6, k4 = (slot & 63) << 2;
        const float* Wsrc = (row < 32) ? Wk : (row < 64 ? Wv : Wq);
        float4 w4 = *(const float4*)&Wsrc[(row & 31)*DD + k4];
        uint2 p; p.x = packbf(w4.x, w4.y); p.y = packbf(w4.z, w4.w);
        *(uint2*)&sW[row*264 + k4] = p;
    }

    __syncthreads();           // Dcs visible
    if (tid < 2) {
        float p = 1.f;
        #pragma unroll
        for (int u = 0; u < 64; u++) { p *= (1.f - Dcs[64*tid + u]); Lam[64*tid + u] = p; }
    }

    // Store X slab 0
    #pragma unroll
    for (int r = 0; r < 8; r++) {
        int slot = tid + 256*r;
        int row = slot >> 4, k4 = (slot & 15) << 2;
        uint2 p; p.x = packbf(R[r].x, R[r].y); p.y = packbf(R[r].z, R[r].w);
        *(uint2*)&sX[row*72 + k4] = p;
    }
    __syncthreads();           // X slab 0 + W + Lam all visible

    const int wy = w >> 1, wx = w & 1;   // warp tile: 32 rows x 48 cols
    float acc[2][6][4];
    #pragma unroll
    for (int mi = 0; mi < 2; mi++)
        #pragma unroll
        for (int ni = 0; ni < 6; ni++)
            #pragma unroll
            for (int r = 0; r < 4; r++) acc[mi][ni][r] = 0.f;

    #pragma unroll
    for (int it = 0; it < 4; it++) {
        // Prefetch next X slab (LDG in flight during MMA section)
        if (it < 3) {
            int kk0n = (it+1) * 64;
            #pragma unroll
            for (int r = 0; r < 8; r++) {
                int slot = tid + 256*r;
                int row = slot >> 4, k4 = (slot & 15) << 2;
                R[r] = *(const float4*)&X[(size_t)(t0+row)*DD + kk0n + k4];
            }
        }
        // MMA over current slab (LDSM fragment loads)
        #pragma unroll
        for (int ks = 0; ks < 4; ks++) {
            int kbX = ks * 16;
            int kbW = it * 64 + ks * 16;
            uint32_t a[2][4];
            #pragma unroll
            for (int mi = 0; mi < 2; mi++) {
                int rb = wy*32 + mi*16;
                ldsm_x4(a[mi], sX32 + ((rb + al)*72 + kbX + ah)*2);
            }
            #pragma unroll
            for (int ni = 0; ni < 6; ni++) {
                int nb = wx*48 + ni*8;
                uint32_t b[2];
                ldsm_x2(b, sW32 + ((nb + bl)*264 + kbW + bh)*2);
                mma16816(acc[0][ni], a[0], b);
                mma16816(acc[1][ni], a[1], b);
            }
        }
        if (it < 3) {
            __syncthreads();   // all warps done reading sX
            #pragma unroll
            for (int r = 0; r < 8; r++) {
                int slot = tid + 256*r;
                int row = slot >> 4, k4 = (slot & 15) << 2;
                uint2 p; p.x = packbf(R[r].x, R[r].y); p.y = packbf(R[r].z, R[r].w);
                *(uint2*)&sX[row*72 + k4] = p;
            }
            __syncthreads();
        }
    }
    __syncthreads();   // last MMA reads done before epilogue overwrites sX

    // Epilogue: scale + write K~/V^T/Q~; KsT/VsT alias sX (all reads done)
    __nv_bfloat16* KsT = sX;               // [2][32][72]  K~^T per chunk
    __nv_bfloat16* VsT = sX + 2*32*72;     // [2][32][72]  V^T per chunk
    #pragma unroll
    for (int mi = 0; mi < 2; mi++) {
        int rlo = wy*32 + mi*16 + g, rhi = rlo + 8;
        float lamL = Lam[rlo], lamH = Lam[rhi];
        float ksL = Lrs[rlo]/lamL, ksH = Lrs[rhi]/lamH;
        int chL = rlo >> 6, ulL = rlo & 63;
        int chH = rhi >> 6, ulH = rhi & 63;
        size_t tL = (size_t)(t0+rlo)*RR, tH = (size_t)(t0+rhi)*RR;
        #pragma unroll
        for (int ni = 0; ni < 6; ni++) {
            int c0 = wx*48 + ni*8 + 2*tig;
            float v0 = acc[mi][ni][0] + bcat[c0];
            float v1 = acc[mi][ni][1] + bcat[c0+1];
            float v2 = acc[mi][ni][2] + bcat[c0];
            float v3 = acc[mi][ni][3] + bcat[c0+1];
            if (c0 < 32) {
                v0 *= ksL; v1 *= ksL; v2 *= ksH; v3 *= ksH;
                *(uint32_t*)&g_Kb[tL + c0] = packbf(v0, v1);
                *(uint32_t*)&g_Kb[tH + c0] = packbf(v2, v3);
                KsT[(chL*32 + c0  )*72 + ulL] = __float2bfloat16(v0);
                KsT[(chL*32 + c0+1)*72 + ulL] = __float2bfloat16(v1);
                KsT[(chH*32 + c0  )*72 + ulH] = __float2bfloat16(v2);
                KsT[(chH*32 + c0+1)*72 + ulH] = __float2bfloat16(v3);
            } else if (c0 < 64) {
                int j0 = c0 - 32;
                __nv_bfloat16 b0 = __float2bfloat16(v0);
                __nv_bfloat16 b1 = __float2bfloat16(v1);
                __nv_bfloat16 b2 = __float2bfloat16(v2);
                __nv_bfloat16 b3 = __float2bfloat16(v3);
                VsT[(chL*32 + j0  )*72 + ulL] = b0;
                VsT[(chL*32 + j0+1)*72 + ulL] = b1;
                VsT[(chH*32 + j0  )*72 + ulH] = b2;
                VsT[(chH*32 + j0+1)*72 + ulH] = b3;
                size_t vbL = (size_t)(blockIdx.x*2 + chL)*2048;
                size_t vbH = (size_t)(blockIdx.x*2 + chH)*2048;
                g_VTb[vbL + (j0  )*64 + ulL] = b0;
                g_VTb[vbL + (j0+1)*64 + ulL] = b1;
                g_VTb[vbH + (j0  )*64 + ulH] = b2;
                g_VTb[vbH + (j0+1)*64 + ulH] = b3;
            } else {
                int r0 = c0 - 64;
                *(uint32_t*)&g_Qb[tL + r0] = packbf(v0*lamL, v1*lamL);
                *(uint32_t*)&g_Qb[tH + r0] = packbf(v2*lamH, v3*lamH);
            }
        }
    }
    __syncthreads();

    // B^T = (K~^T V)^T via MMA: per chunk 4 warps, warp tile m16 x n16, k=64
    {
        int ch = w >> 2, wl = w & 3;
        int wy2 = wl >> 1, wx2 = wl & 1;
        const uint32_t kt32 = sptr(KsT + ch*32*72);
        const uint32_t vt32 = sptr(VsT + ch*32*72);
        float accB[2][4];
        #pragma unroll
        for (int ni = 0; ni < 2; ni++)
            #pragma unroll
            for (int r = 0; r < 4; r++) accB[ni][r] = 0.f;
        #pragma unroll
        for (int ks = 0; ks < 4; ks++) {
            int kb = ks * 16;
            int rb2 = wy2 * 16;
            uint32_t a[4];
            ldsm_x4(a, kt32 + ((rb2 + al)*72 + kb + ah)*2);
            #pragma unroll
            for (int ni = 0; ni < 2; ni++) {
                int nb = wx2*16 + ni*8;
                uint32_t b[2];
                ldsm_x2(b, vt32 + ((nb + bl)*72 + kb + bh)*2);
                mma16816(accB[ni], a, b);
            }
        }
        int cg = blockIdx.x*2 + ch;
        size_t base = (size_t)cg * 1024;
        #pragma unroll
        for (int ni = 0; ni < 2; ni++) {
            int i0 = wy2*16 + g, i1 = i0 + 8;
            int j0 = wx2*16 + ni*8 + 2*tig;
            g_BT[base + (j0  )*32 + i0] = accB[ni][0];
            g_BT[base + (j0+1)*32 + i0] = accB[ni][1];
            g_BT[base + (j0  )*32 + i1] = accB[ni][2];
            g_BT[base + (j0+1)*32 + i1] = accB[ni][3];
        }
        if (wl == 0 && lane == 0) g_gm[cg] = Lam[ch*64 + 63];
    }
}

// ---------------------------------------------------------------------------
// Scan phase A: per-segment local carry (zero init), depth 16.
// ---------------------------------------------------------------------------
__global__ __launch_bounds__(1024, 1) void k_scan_a()
{
    __shared__ float gs[SEG];
    const int b = blockIdx.x, e = threadIdx.x;
    if (e < SEG) gs[e] = g_gm[b*SEG + e];
    __syncthreads();
    const float* Bp = g_BT + (size_t)b*SEG*1024 + e;
    float bvv[SEG];
    #pragma unroll
    for (int c = 0; c < SEG; c++) bvv[c] = Bp[(size_t)c*1024];
    float s = 0.f;
    #pragma unroll
    for (int c = 0; c < SEG; c++) s = gs[c] * (s + bvv[c]);
    g_carry[(size_t)b*1024 + e] = s;
}

// ---------------------------------------------------------------------------
// Kernel 3 (fused with scan phase B): 4 chunks/block, grid 256 = single wave.
// ---------------------------------------------------------------------------
__global__ __launch_bounds__(256, 3) void k_out(
    const float* __restrict__ Wo, const float* __restrict__ bo,
    float* __restrict__ out)
{
    extern __shared__ __align__(16) __nv_bfloat16 osm[];
    __nv_bfloat16* sQ  = osm;                 // 4*64*40 = 10240
    __nv_bfloat16* sK  = sQ  + 10240;         // 10240
    __nv_bfloat16* sVT = sK  + 10240;         // 4*32*72 = 9216
    __nv_bfloat16* sST = sVT + 9216;          // 4*32*40 = 5120
    __nv_bfloat16* sWo = sST + 5120;          // 56*40   = 2240
    __shared__ float sbo[56];
    __shared__ float sAs[NSEG];
    __shared__ float gsc[SEG];

    const int tid   = threadIdx.x;
    const int cg0   = blockIdx.x * 4;         // first chunk of this block
    const int b_seg = blockIdx.x >> 2;        // segment index
    const int p0    = (blockIdx.x & 3) * 4;   // seg-local offset of cg0

    if (tid < NSEG) {
        float pp = 1.f;
        #pragma unroll
        for (int c = 0; c < SEG; c++) pp *= g_gm[tid*SEG + c];
        sAs[tid] = pp;
    } else if (tid < NSEG + SEG) {
        gsc[tid - NSEG] = g_gm[b_seg*SEG + (tid - NSEG)];
    } else if (tid < NSEG + SEG + 56) {
        int m = tid - NSEG - SEG;
        sbo[m] = (m < MM) ? bo[m] : 0.f;
    }

    #pragma unroll
    for (int r = 0; r < 8; r++) {
        int slot = tid + 256*r;                 // 2048 slots
        int ch = slot >> 9, s = slot & 511;
        int row = s >> 3, c4 = (s & 7) << 2;
        size_t gi = ((size_t)(cg0+ch)*64 + row)*RR + c4;
        *(uint2*)&sQ[(ch*64+row)*40 + c4] = *(const uint2*)&g_Qb[gi];
        *(uint2*)&sK[(ch*64+row)*40 + c4] = *(const uint2*)&g_Kb[gi];
    }
    #pragma unroll
    for (int r = 0; r < 8; r++) {
        int slot = tid + 256*r;                 // 2048 slots
        int ch = slot >> 9, s = slot & 511;
        int row = s >> 4, c4 = (s & 15) << 2;
        *(uint2*)&sVT[(ch*32+row)*72 + c4] =
            *(const uint2*)&g_VTb[(size_t)(cg0+ch)*2048 + row*64 + c4];
    }
    #pragma unroll
    for (int r = 0; r < 7; r++) {
        int idx = tid + 256*r;                  // 1792 = 56*32
        int m = idx >> 5, jj = idx & 31;
        sWo[m*40 + jj] = __float2bfloat16(m < MM ? Wo[m*RR + jj] : 0.f);
    }
    __syncthreads();

    // ---- Fold carries of preceding segments
    float pf[4] = {0.f, 0.f, 0.f, 0.f};
    for (int bb = 0; bb < b_seg; bb += 8) {
        float4 cv[8]; float av[8];
        #pragma unroll
        for (int jq = 0; jq < 8; jq++) {
            bool ok = (bb + jq) < b_seg;
            cv[jq] = ok ? *(const float4*)&g_carry[(size_t)(bb+jq)*1024 + tid*4]
                        : make_float4(0.f, 0.f, 0.f, 0.f);
            av[jq] = ok ? sAs[bb+jq] : 1.f;
        }
        #pragma unroll
        for (int jq = 0; jq < 8; jq++) {
            pf[0] = fmaf(av[jq], pf[0], cv[jq].x);
            pf[1] = fmaf(av[jq], pf[1], cv[jq].y);
            pf[2] = fmaf(av[jq], pf[2], cv[jq].z);
            pf[3] = fmaf(av[jq], pf[3], cv[jq].w);
        }
    }
    // ---- Replay seg-local chunks 0..p0-1
    for (int cc = 0; cc < p0; cc += 4) {
        float4 bv[4];
        #pragma unroll
        for (int jq = 0; jq < 4; jq++)
            bv[jq] = *(const float4*)&g_BT[(size_t)(b_seg*SEG + cc + jq)*1024 + tid*4];
        #pragma unroll
        for (int jq = 0; jq < 4; jq++) {
            float gv = gsc[cc + jq];
            pf[0] = gv*(pf[0] + bv[jq].x);
            pf[1] = gv*(pf[1] + bv[jq].y);
            pf[2] = gv*(pf[2] + bv[jq].z);
            pf[3] = gv*(pf[3] + bv[jq].w);
        }
    }
    // ---- Emit 4 incoming states into sST (bf16)
    {
        const int jrow = tid >> 3, i0 = (tid & 7) << 2;
        float4 b3[3];
        #pragma unroll
        for (int q = 0; q < 3; q++)
            b3[q] = *(const float4*)&g_BT[(size_t)(cg0 + q)*1024 + tid*4];
        __nv_bfloat16* d0 = &sST[(0*32 + jrow)*40 + i0];
        *(uint32_t*)&d0[0] = packbf(pf[0], pf[1]);
        *(uint32_t*)&d0[2] = packbf(pf[2], pf[3]);
        #pragma unroll
        for (int q = 0; q < 3; q++) {
            float gv = gsc[p0 + q];
            pf[0] = gv*(pf[0] + b3[q].x);
            pf[1] = gv*(pf[1] + b3[q].y);
            pf[2] = gv*(pf[2] + b3[q].z);
            pf[3] = gv*(pf[3] + b3[q].w);
            __nv_bfloat16* d = &sST[((q+1)*32 + jrow)*40 + i0];
            *(uint32_t*)&d[0] = packbf(pf[0], pf[1]);
            *(uint32_t*)&d[2] = packbf(pf[2], pf[3]);
        }
    }
    __syncthreads();

    // ---- MMA phase: 8 warps, each does 2 chunks sequentially (LDSM frags)
    const int lane = tid & 31, w = tid >> 5;
    const int g = lane >> 2, tig = lane & 3;
    const int al = lane & 15, ah = 8*(lane >> 4);
    const int bl = lane & 7,  bh = 8*((lane >> 3) & 1);
    const int rb = (w & 3) * 16;

    for (int ch2 = 0; ch2 < 2; ch2++) {
        const int ci = (w >> 2)*2 + ch2;
        const uint32_t q32  = sptr(sQ  + ci*2560);
        const uint32_t k32  = sptr(sK  + ci*2560);
        const uint32_t vt32 = sptr(sVT + ci*2304);
        const uint32_t st32 = sptr(sST + ci*1280);
        const uint32_t wo32 = sptr(sWo);

        uint32_t aq[2][4];
        float accA[8][4];
        #pragma unroll
        for (int ni = 0; ni < 8; ni++)
            #pragma unroll
            for (int r = 0; r < 4; r++) accA[ni][r] = 0.f;
        #pragma unroll
        for (int ks = 0; ks < 2; ks++) {
            int kb = ks * 16;
            ldsm_x4(aq[ks], q32 + ((rb + al)*40 + kb + ah)*2);
            #pragma unroll
            for (int ni = 0; ni < 8; ni++) {
                uint32_t b[2];
                ldsm_x2(b, k32 + ((ni*8 + bl)*40 + kb + bh)*2);
                mma16816(accA[ni], aq[ks], b);
            }
        }
        uint32_t aA[4][4];
        {
            int ulo = rb + g, uhi = rb + g + 8;
            #pragma unroll
            for (int ni = 0; ni < 8; ni++) {
                int s0 = ni*8 + 2*tig, s1 = s0 + 1;
                float m0 = (s0 <= ulo) ? accA[ni][0] : 0.f;
                float m1 = (s1 <= ulo) ? accA[ni][1] : 0.f;
                float m2 = (s0 <= uhi) ? accA[ni][2] : 0.f;
                float m3 = (s1 <= uhi) ? accA[ni][3] : 0.f;
                int ks2 = ni >> 1;
                if ((ni & 1) == 0) { aA[ks2][0] = packbf(m0, m1); aA[ks2][1] = packbf(m2, m3); }
                else               { aA[ks2][2] = packbf(m0, m1); aA[ks2][3] = packbf(m2, m3); }
            }
        }
        float accO[4][4];
        #pragma unroll
        for (int ni = 0; ni < 4; ni++)
            #pragma unroll
            for (int r = 0; r < 4; r++) accO[ni][r] = 0.f;
        #pragma unroll
        for (int ks = 0; ks < 2; ks++) {
            int kb = ks * 16;
            #pragma unroll
            for (int ni = 0; ni < 4; ni++) {
                uint32_t b[2];
                ldsm_x2(b, st32 + ((ni*8 + bl)*40 + kb + bh)*2);
                mma16816(accO[ni], aq[ks], b);
            }
        }
        #pragma unroll
        for (int ks = 0; ks < 4; ks++) {
            int kb = ks * 16;
            #pragma unroll
            for (int ni = 0; ni < 4; ni++) {
                uint32_t b[2];
                ldsm_x2(b, vt32 + ((ni*8 + bl)*72 + kb + bh)*2);
                mma16816(accO[ni], aA[ks], b);
            }
        }
        uint32_t aO[2][4];
        #pragma unroll
        for (int ks2 = 0; ks2 < 2; ks2++) {
            aO[ks2][0] = packbf(accO[2*ks2  ][0], accO[2*ks2  ][1]);
            aO[ks2][1] = packbf(accO[2*ks2  ][2], accO[2*ks2  ][3]);
            aO[ks2][2] = packbf(accO[2*ks2+1][0], accO[2*ks2+1][1]);
            aO[ks2][3] = packbf(accO[2*ks2+1][2], accO[2*ks2+1][3]);
        }
        float accH[7][4];
        #pragma unroll
        for (int ni = 0; ni < 7; ni++)
            #pragma unroll
            for (int r = 0; r < 4; r++) accH[ni][r] = 0.f;
        #pragma unroll
        for (int ks = 0; ks < 2; ks++) {
            int kb = ks * 16;
            #pragma unroll
            for (int ni = 0; ni < 7; ni++) {
                uint32_t b[2];
                ldsm_x2(b, wo32 + ((ni*8 + bl)*40 + kb + bh)*2);
                mma16816(accH[ni], aO[ks], b);
            }
        }
        {
            size_t t0c = (size_t)(cg0 + ci) * 64;
            size_t rl = (t0c + rb + g) * MM;
            size_t rh = (t0c + rb + g + 8) * MM;
            #pragma unroll
            for (int ni = 0; ni < 7; ni++) {
                int m0 = ni*8 + 2*tig, m1 = m0 + 1;
                if (m0 < MM) {
                    out[rl + m0] = 1.f + tanh_fast(accH[ni][0] + sbo[m0]);
                    out[rh + m0] = 1.f + tanh_fast(accH[ni][2] + sbo[m0]);
                }
                if (m1 < MM) {
                    out[rl + m1] = 1.f + tanh_fast(accH[ni][1] + sbo[m1]);
                    out[rh + m1] = 1.f + tanh_fast(accH[ni][3] + sbo[m1]);
                }
            }
        }
    }
}

// ---------------------------------------------------------------------------
extern "C" void kernel_launch(void* const* d_in, const int* in_sizes, int n_in,
                              void* d_out, int out_size)
{
    const float* X  = (const float*)d_in[0];
    const float* lr = (const float*)d_in[1];
    const float* dc = (const float*)d_in[2];
    const float* Wk = (const float*)d_in[3];
    const float* bk = (const float*)d_in[4];
    const float* Wv = (const float*)d_in[5];
    const float* bv = (const float*)d_in[6];
    const float* Wq = (const float*)d_in[7];
    const float* bq = (const float*)d_in[8];
    const float* Wo = (const float*)d_in[9];
    const float* bo = (const float*)d_in[10];
    float* out = (float*)d_out;

    const int smem1 = (96*264 + 128*72) * 2;                      // 69120 B
    const int smem3 = (10240 + 10240 + 9216 + 5120 + 2240) * 2;   // 74112 B
    cudaFuncSetAttribute(k_proj, cudaFuncAttributeMaxDynamicSharedMemorySize, smem1);
    cudaFuncSetAttribute(k_out,  cudaFuncAttributeMaxDynamicSharedMemorySize, smem3);

    k_proj<<<NCK/2, 256, smem1>>>(X, lr, dc, Wk, bk, Wv, bv, Wq, bq);
    k_scan_a<<<NSEG, 1024>>>();
    k_out<<<NCK/4, 256, smem3>>>(Wo, bo, out);
    (void)in_sizes; (void)n_in; (void)out_size;
}